// round 4
// baseline (speedup 1.0000x reference)
#include <cuda_runtime.h>

// DynamicNet_17695265259799 — exact closed form of the reference.
//
// reference(): Wm = tril(W,-1) keeps W[i,j] only for i > j, but the scan
// fills nodes j = 1..n-1 in ASCENDING order, so at step j every potential
// source activation A[:,i], i > j is still exactly 0.0f. Hence
// s_j == b[j] exactly (0 * finite == 0 in IEEE fp32), the output node is
// linear, and the result is b[n-1] broadcast over the batch — independent
// of x and W for all finite inputs.
//
// R4: latency/ramp-bound, not issue-bound (R3 lesson). Max warps in flight
// (8192), one STG.128 each, small CTAs (128 thr) for fine-grained CTA
// distribution, bias pointer pre-offset on host.

__global__ __launch_bounds__(128)
void dynamicnet_broadcast_kernel(const float* __restrict__ bias_last,
                                 float4* __restrict__ out4,
                                 int n4) {
    // Issue the broadcast load immediately; zero index math ahead of it.
    const float v = __ldg(bias_last);
    const int tid = blockIdx.x * blockDim.x + threadIdx.x;
    const float4 v4 = make_float4(v, v, v, v);
    if (tid < n4) out4[tid] = v4;
}

// Scalar tail for out_size % 4 != 0 (not hit for out_size = 1048576).
__global__ void dynamicnet_tail_kernel(const float* __restrict__ bias_last,
                                       float* __restrict__ out,
                                       int start, int out_elems) {
    const float v = __ldg(bias_last);
    int i = start + threadIdx.x;
    if (i < out_elems) out[i] = v;
}

extern "C" void kernel_launch(void* const* d_in, const int* in_sizes, int n_in,
                              void* d_out, int out_size) {
    // metadata order: x [BATCH,1] f32, W [n,n] f32, b [n] f32
    const float* bias = (const float*)d_in[2];
    const int n_nodes = in_sizes[2];  // 66
    const float* bias_last = bias + (n_nodes - 1);

    float* out = (float*)d_out;
    const int n4 = out_size >> 2;  // 262144 float4 slots

    const int threads = 128;
    int blocks = (n4 + threads - 1) / threads;  // 2048 blocks
    if (blocks < 1) blocks = 1;

    dynamicnet_broadcast_kernel<<<blocks, threads>>>(
        bias_last, reinterpret_cast<float4*>(out), n4);

    const int tail = out_size - (n4 << 2);
    if (tail > 0) {
        dynamicnet_tail_kernel<<<1, 32>>>(bias_last, out, n4 << 2, out_size);
    }
}